// round 9
// baseline (speedup 1.0000x reference)
#include <cuda_runtime.h>
#include <cstdint>

typedef unsigned long long ULL;

// ---------- packed fp32x2 helpers ----------
__device__ __forceinline__ void ffma2(ULL &d, ULL a, ULL b) {
    asm("fma.rn.f32x2 %0, %1, %2, %0;" : "+l"(d) : "l"(a), "l"(b));
}
__device__ __forceinline__ float2 unpack2(ULL v) {
    float2 f; asm("mov.b64 {%0,%1}, %2;" : "=f"(f.x), "=f"(f.y) : "l"(v)); return f;
}
__device__ __forceinline__ ULL pack2(float lo, float hi) {
    ULL r; asm("mov.b64 %0, {%1,%2};" : "=l"(r) : "f"(lo), "f"(hi)); return r;
}

// ---------- activations: single-MUFU tanh ----------
__device__ __forceinline__ float tanh_ap(float x) {
    float r; asm("tanh.approx.f32 %0, %1;" : "=f"(r) : "f"(x)); return r;
}
__device__ __forceinline__ float sig_ap(float x) {
    return fmaf(0.5f, tanh_ap(0.5f * x), 0.5f);
}

// ---------- tf32 rounding ----------
__device__ __forceinline__ float tf32r(float x) {
    uint32_t r; asm("cvt.rna.tf32.f32 %0, %1;" : "=r"(r) : "f"(x));
    return __uint_as_float(r);
}

// ---------- cp.async 16B ----------
__device__ __forceinline__ void cp16(uint32_t dst_smem, const void* src) {
    asm volatile("cp.async.cg.shared.global [%0], [%1], 16;" :: "r"(dst_smem), "l"(src) : "memory");
}
__device__ __forceinline__ void cp_commit() { asm volatile("cp.async.commit_group;"); }
__device__ __forceinline__ void cp_wait0()  { asm volatile("cp.async.wait_group 0;" ::: "memory"); }

// ---------- constants ----------
constexpr int B = 512, T = 512;
constexpr long BT = (long)B * T;
constexpr int RC = 4;

// ---------- scratch ----------
__device__ __align__(16) float g_h0T[128 * BT];   // layer-0 out (tf32-rounded), [k][b*T+t]
__device__ __align__(16) float g_xp1[BT * 512];   // layer-1 preacts [b*T+t][n]
__device__ __align__(16) float g_BtT[128 * 512];  // Wih_l1^T (tf32-rounded) [k][n]
__device__ float g_pooled[B * 128];

// =======================================================================
// Layer-0 biLSTM (R5/R7-exact, PROTECTED). grid (128, 2), block 256, 2 CTAs/SM.
// =======================================================================
__global__ __launch_bounds__(256, 2) void lstm_l0(
    const float* __restrict__ x,
    const float* __restrict__ Wih_f, const float* __restrict__ Whh_f, const float* __restrict__ b_f,
    const float* __restrict__ Wih_b, const float* __restrict__ Whh_b, const float* __restrict__ b_b)
{
    const int dir = blockIdx.y;
    const int b0  = blockIdx.x * RC;
    const int tid = threadIdx.x;
    const int u   = tid >> 2;
    const int g   = tid & 3;
    const int row = g * 64 + u;

    const float* Wih = dir ? Wih_b : Wih_f;
    const float* Whh = dir ? Whh_b : Whh_f;
    const float* bb  = dir ? b_b   : b_f;

    __shared__ __align__(16) float h_s[2][RC * 64];
    __shared__ __align__(16) float4 x_s[2][RC];
    __shared__ __align__(16) float hist[RC][64][36];

    ULL w2[32];
    {
        const ULL* wp = (const ULL*)(Whh + row * 64);
        #pragma unroll
        for (int i = 0; i < 32; i++) w2[i] = wp[i];
    }
    const float4 wih = *(const float4*)(Wih + row * 4);
    const float bias = bb[row];

    const int lane = tid & 31;
    const int qb   = lane & ~3;

    for (int i = tid; i < RC * 64; i += 256) h_s[0][i] = 0.f;
    if (tid < RC) {
        const int t0 = dir ? (T - 1) : 0;
        x_s[0][tid] = *(const float4*)(x + ((long)(b0 + tid) * T + t0) * 4);
    }
    __syncthreads();

    float c[RC] = {0.f, 0.f, 0.f, 0.f};
    int p = 0;

    for (int s = 0; s < T; s++) {
        const int t = dir ? (T - 1 - s) : s;
        if (tid < RC) {
            const int sn = (s + 1 < T) ? s + 1 : s;
            const int tn = dir ? (T - 1 - sn) : sn;
            x_s[p ^ 1][tid] = *(const float4*)(x + ((long)(b0 + tid) * T + tn) * 4);
        }

        float pre[RC];
        #pragma unroll
        for (int j = 0; j < RC; j++) {
            ULL a0 = 0, a1 = 0;
            const ulonglong2* h4 = (const ulonglong2*)(h_s[p] + j * 64);
            #pragma unroll
            for (int k = 0; k < 16; k++) {
                ulonglong2 hv = h4[k];
                ffma2(a0, w2[2 * k],     hv.x);
                ffma2(a1, w2[2 * k + 1], hv.y);
            }
            const float2 f0 = unpack2(a0), f1 = unpack2(a1);
            const float4 xv = x_s[p][j];
            pre[j] = f0.x + f0.y + f1.x + f1.y + bias
                   + wih.x * xv.x + wih.y * xv.y + wih.z * xv.z + wih.w * xv.w;
        }

        #pragma unroll
        for (int j = 0; j < RC; j++) {
            const float act = (g == 2) ? tanh_ap(pre[j]) : sig_ap(pre[j]);
            const float iv = __shfl_sync(0xffffffffu, act, qb + 0);
            const float fv = __shfl_sync(0xffffffffu, act, qb + 1);
            const float gv = __shfl_sync(0xffffffffu, act, qb + 2);
            const float ov = __shfl_sync(0xffffffffu, act, qb + 3);
            c[j] = fmaf(fv, c[j], iv * gv);
            const float h = ov * tanh_ap(c[j]);
            if (g == 0) {
                h_s[p ^ 1][j * 64 + u] = h;
                hist[j][u][t & 31] = h;
            }
        }
        p ^= 1;
        __syncthreads();

        if ((s & 31) == 31) {
            const int tbase = t & ~31;
            #pragma unroll
            for (int w = 0; w < 8; w++) {
                const int e   = tid + w * 256;
                const int tw4 = e & 7;
                const int ju  = e >> 3;
                const int j   = ju >> 6, uu = ju & 63;
                float4 v = *(const float4*)(&hist[j][uu][tw4 * 4]);
                v.x = tf32r(v.x); v.y = tf32r(v.y); v.z = tf32r(v.z); v.w = tf32r(v.w);
                *(float4*)(g_h0T + (long)(dir * 64 + uu) * BT + (long)(b0 + j) * T + tbase + tw4 * 4) = v;
            }
            __syncthreads();
        }
    }
}

// =======================================================================
// Prep: g_BtT[k][n] = tf32(Wih_l1[n][k])   (n = dir*256 + gate_row)
// =======================================================================
__global__ void prep_btT(const float* __restrict__ Wf, const float* __restrict__ Wb)
{
    const int idx = blockIdx.x * 512 + threadIdx.x;   // 65536
    const int k = idx >> 9, n = idx & 511;
    const float* W = (n & 256) ? Wb : Wf;
    g_BtT[idx] = tf32r(W[(n & 255) * 128 + k]);
}

// =======================================================================
// xp1 GEMM: A-RESIDENT restructure. Each CTA owns 128 m-rows; A tile
// (128k x 128m, 69.6KB) loaded ONCE; loop 4 n-blocks x 8 K-slabs (KS=16,
// double-buffered B via cp.async; B is L2-resident). DRAM traffic:
// 134MB A + 537MB write (A reread eliminated). grid 2048, blk 256, 2 CTAs/SM.
// =======================================================================
constexpr int FP = 136;
constexpr int KS = 16;
constexpr int ASZ = 128 * FP;                    // A floats
constexpr int BSLAB = KS * FP;                   // B slab floats
constexpr int SMEM_GEMM = (ASZ + 2 * BSLAB) * 4; // 87040 B

__global__ __launch_bounds__(256, 2) void gemm_xp1(
    const float* __restrict__ bias_f, const float* __restrict__ bias_b)
{
    extern __shared__ float sm[];        // A[128][FP] | Bbuf[2][KS][FP]
    float* As = sm;
    float* Bb = sm + ASZ;
    const uint32_t smB = (uint32_t)__cvta_generic_to_shared(sm);
    const int tid  = threadIdx.x;
    const int lane = tid & 31;
    const int wid  = tid >> 5;
    const int g    = lane >> 2;
    const int cc   = lane & 3;
    const int wm   = (wid & 3) * 32;
    const int wn   = (wid >> 2) * 64;
    const long m0  = (long)blockIdx.x * 128;

    // ---- A tile: full K=128, loaded once (16 cp16/thread) ----
    #pragma unroll
    for (int i = 0; i < 16; i++) {
        const int e = tid + i * 256;
        const int k = e >> 5, m4 = (e & 31) * 4;
        cp16(smB + (uint32_t)(k * FP + m4) * 4, g_h0T + (long)k * BT + m0 + m4);
    }

    // ---- B slab loader: slab si = nb*8 + kc ----
    auto load_b = [&](int buf, int si) {
        const int nb = si >> 3, kc = si & 7;
        #pragma unroll
        for (int i = 0; i < 2; i++) {
            const int e = tid + i * 256;
            const int k = e >> 5, n4 = (e & 31) * 4;
            cp16(smB + (uint32_t)(ASZ + buf * BSLAB + k * FP + n4) * 4,
                 g_BtT + (long)(kc * KS + k) * 512 + nb * 128 + n4);
        }
    };

    load_b(0, 0);
    cp_commit();              // group: A + B slab 0

    float acc[2][8][4];
    #pragma unroll
    for (int i = 0; i < 2; i++)
        #pragma unroll
        for (int j = 0; j < 8; j++)
            #pragma unroll
            for (int q = 0; q < 4; q++) acc[i][j][q] = 0.f;

    int buf = 0;
    for (int si = 0; si < 32; si++) {
        cp_wait0();
        __syncthreads();                       // slab `buf` (and A on si=0) ready
        if (si < 31) { load_b(buf ^ 1, si + 1); cp_commit(); }

        const int kc = si & 7;
        const float* Bs = Bb + buf * BSLAB;
        #pragma unroll
        for (int kk = 0; kk < 2; kk++) {
            const float* abase = As + (kc * KS + kk * 8 + cc) * FP + wm + g;
            uint32_t a0[2], a1[2], a2[2], a3[2];
            #pragma unroll
            for (int i = 0; i < 2; i++) {
                const float* ap = abase + 16 * i;
                a0[i] = __float_as_uint(ap[0]);
                a1[i] = __float_as_uint(ap[8]);
                a2[i] = __float_as_uint(ap[4 * FP]);
                a3[i] = __float_as_uint(ap[4 * FP + 8]);
            }
            const float* bbase = Bs + (kk * 8 + cc) * FP + wn + g;
            uint32_t b0[8], b1[8];
            #pragma unroll
            for (int j = 0; j < 8; j++) {
                b0[j] = __float_as_uint(bbase[8 * j]);
                b1[j] = __float_as_uint(bbase[8 * j + 4 * FP]);
            }
            #pragma unroll
            for (int i = 0; i < 2; i++)
                #pragma unroll
                for (int j = 0; j < 8; j++) {
                    asm("mma.sync.aligned.m16n8k8.row.col.f32.tf32.tf32.f32 "
                        "{%0,%1,%2,%3}, {%4,%5,%6,%7}, {%8,%9}, {%0,%1,%2,%3};"
                        : "+f"(acc[i][j][0]), "+f"(acc[i][j][1]),
                          "+f"(acc[i][j][2]), "+f"(acc[i][j][3])
                        : "r"(a0[i]), "r"(a1[i]), "r"(a2[i]), "r"(a3[i]),
                          "r"(b0[j]), "r"(b1[j]));
                }
        }
        buf ^= 1;

        if (kc == 7) {
            // ---- epilogue for n-block nb: + bias, ULL stores; reset acc ----
            const int nb = si >> 3;
            const int n0 = nb * 128;
            const float* bp = (n0 & 256) ? bias_b : bias_f;
            #pragma unroll
            for (int i = 0; i < 2; i++) {
                const long mrow = m0 + wm + 16 * i + g;
                float* r0 = g_xp1 + mrow * 512;
                float* r1 = r0 + 8 * 512;
                #pragma unroll
                for (int j = 0; j < 8; j++) {
                    const int n = n0 + wn + 8 * j + cc * 2;
                    const float bn0 = bp[n & 255];
                    const float bn1 = bp[(n + 1) & 255];
                    *(ULL*)(r0 + n) = pack2(acc[i][j][0] + bn0, acc[i][j][1] + bn1);
                    *(ULL*)(r1 + n) = pack2(acc[i][j][2] + bn0, acc[i][j][3] + bn1);
                    acc[i][j][0] = 0.f; acc[i][j][1] = 0.f;
                    acc[i][j][2] = 0.f; acc[i][j][3] = 0.f;
                }
            }
        }
        __syncthreads();                       // all warps done with slab before reuse
    }
}

// =======================================================================
// Layer-1 biLSTM (R8-exact, PROTECTED). grid (128, 2), block 256, 2 CTAs/SM.
// =======================================================================
__global__ __launch_bounds__(256, 2) void lstm_l1(
    const float* __restrict__ Whh_f, const float* __restrict__ Whh_b)
{
    const int dir = blockIdx.y;
    const int b0  = blockIdx.x * RC;
    const int tid = threadIdx.x;
    const int u   = tid >> 2;
    const int g   = tid & 3;
    const int row = g * 64 + u;
    const float* Whh = dir ? Whh_b : Whh_f;

    __shared__ __align__(16) float h_s[2][RC * 64];
    __shared__ __align__(16) float xp_s[2][RC][4][72];

    ULL w2[32];
    {
        const ULL* wp = (const ULL*)(Whh + row * 64);
        #pragma unroll
        for (int i = 0; i < 32; i++) w2[i] = wp[i];
    }
    const int lane = tid & 31;
    const int qb   = lane & ~3;

    const int j_st  = tid >> 6;
    const int c_st  = tid & 63;
    const int g_st  = c_st >> 4;
    const int u4_st = (c_st & 15) * 4;
    const uint32_t xpsB = (uint32_t)__cvta_generic_to_shared(&xp_s[0][0][0][0]);
    const uint32_t st_off = (uint32_t)(((j_st * 4 + g_st) * 72 + u4_st) * 4);
    const uint32_t buf_stride = (uint32_t)(RC * 4 * 72 * 4);
    const float* xp_src = g_xp1 + (long)(b0 + j_st) * T * 512 + dir * 256 + c_st * 4;

    for (int i = tid; i < RC * 64; i += 256) h_s[0][i] = 0.f;

    float c[RC]    = {0.f, 0.f, 0.f, 0.f};
    float hsum[RC] = {0.f, 0.f, 0.f, 0.f};
    {
        const int t0 = dir ? (T - 1) : 0;
        cp16(xpsB + st_off, xp_src + (long)t0 * 512);
        cp_commit();
        cp_wait0();
    }
    __syncthreads();

    int p = 0;
    for (int s = 0; s < T; s++) {
        if (s + 1 < T) {
            const int tn = dir ? (T - 2 - s) : (s + 1);
            cp16(xpsB + (p ^ 1) * buf_stride + st_off, xp_src + (long)tn * 512);
            cp_commit();
        }

        float pre[RC];
        #pragma unroll
        for (int j = 0; j < RC; j++) {
            ULL a0 = 0, a1 = 0;
            const ulonglong2* h4 = (const ulonglong2*)(h_s[p] + j * 64);
            #pragma unroll
            for (int k = 0; k < 16; k++) {
                ulonglong2 hv = h4[k];
                ffma2(a0, w2[2 * k],     hv.x);
                ffma2(a1, w2[2 * k + 1], hv.y);
            }
            const float2 f0 = unpack2(a0), f1 = unpack2(a1);
            pre[j] = f0.x + f0.y + f1.x + f1.y + xp_s[p][j][g][u];
        }

        #pragma unroll
        for (int j = 0; j < RC; j++) {
            const float act = (g == 2) ? tanh_ap(pre[j]) : sig_ap(pre[j]);
            const float iv = __shfl_sync(0xffffffffu, act, qb + 0);
            const float fv = __shfl_sync(0xffffffffu, act, qb + 1);
            const float gv = __shfl_sync(0xffffffffu, act, qb + 2);
            const float ov = __shfl_sync(0xffffffffu, act, qb + 3);
            c[j] = fmaf(fv, c[j], iv * gv);
            const float h = ov * tanh_ap(c[j]);
            hsum[j] += h;
            if (g == 0) h_s[p ^ 1][j * 64 + u] = h;
        }
        cp_wait0();
        p ^= 1;
        __syncthreads();
    }

    if (g == 0) {
        #pragma unroll
        for (int j = 0; j < RC; j++)
            g_pooled[(b0 + j) * 128 + dir * 64 + u] = hsum[j];
    }
}

// =======================================================================
__global__ void fc_kernel(const float* __restrict__ fcw, const float* __restrict__ fcb,
                          float* __restrict__ out)
{
    const int gw   = (blockIdx.x * blockDim.x + threadIdx.x) >> 5;
    const int lane = threadIdx.x & 31;
    if (gw >= B) return;
    float sum = 0.f;
    #pragma unroll
    for (int qq = 0; qq < 4; qq++)
        sum += g_pooled[gw * 128 + qq * 32 + lane] * fcw[qq * 32 + lane];
    #pragma unroll
    for (int o = 16; o; o >>= 1) sum += __shfl_xor_sync(0xffffffffu, sum, o);
    if (lane == 0) out[gw] = sum * (1.f / 512.f) + fcb[0];
}

// =======================================================================
extern "C" void kernel_launch(void* const* d_in, const int* in_sizes, int n_in,
                              void* d_out, int out_size)
{
    const float* x     = (const float*)d_in[0];
    const float* Wih0f = (const float*)d_in[1];
    const float* Whh0f = (const float*)d_in[2];
    const float* b0f   = (const float*)d_in[3];
    const float* Wih0b = (const float*)d_in[4];
    const float* Whh0b = (const float*)d_in[5];
    const float* b0b   = (const float*)d_in[6];
    const float* Wih1f = (const float*)d_in[7];
    const float* Whh1f = (const float*)d_in[8];
    const float* b1f   = (const float*)d_in[9];
    const float* Wih1b = (const float*)d_in[10];
    const float* Whh1b = (const float*)d_in[11];
    const float* b1b   = (const float*)d_in[12];
    const float* fcw   = (const float*)d_in[13];
    const float* fcb   = (const float*)d_in[14];

    prep_btT<<<128, 512>>>(Wih1f, Wih1b);
    lstm_l0<<<dim3(B / RC, 2), 256>>>(x, Wih0f, Whh0f, b0f, Wih0b, Whh0b, b0b);
    cudaFuncSetAttribute(gemm_xp1, cudaFuncAttributeMaxDynamicSharedMemorySize, SMEM_GEMM);
    gemm_xp1<<<2048, 256, SMEM_GEMM>>>(b1f, b1b);
    lstm_l1<<<dim3(B / RC, 2), 256>>>(Whh1f, Whh1b);
    fc_kernel<<<32, 512>>>(fcw, fcb, (float*)d_out);
}

// round 10
// speedup vs baseline: 1.6237x; 1.6237x over previous
#include <cuda_runtime.h>
#include <cstdint>

typedef unsigned long long ULL;

// ---------- packed fp32x2 helpers ----------
__device__ __forceinline__ void ffma2(ULL &d, ULL a, ULL b) {
    asm("fma.rn.f32x2 %0, %1, %2, %0;" : "+l"(d) : "l"(a), "l"(b));
}
__device__ __forceinline__ float2 unpack2(ULL v) {
    float2 f; asm("mov.b64 {%0,%1}, %2;" : "=f"(f.x), "=f"(f.y) : "l"(v)); return f;
}
__device__ __forceinline__ ULL pack2(float lo, float hi) {
    ULL r; asm("mov.b64 %0, {%1,%2};" : "=l"(r) : "f"(lo), "f"(hi)); return r;
}

// ---------- activations: single-MUFU tanh ----------
__device__ __forceinline__ float tanh_ap(float x) {
    float r; asm("tanh.approx.f32 %0, %1;" : "=f"(r) : "f"(x)); return r;
}
__device__ __forceinline__ float sig_ap(float x) {
    return fmaf(0.5f, tanh_ap(0.5f * x), 0.5f);
}

// ---------- tf32 rounding ----------
__device__ __forceinline__ float tf32r(float x) {
    uint32_t r; asm("cvt.rna.tf32.f32 %0, %1;" : "=r"(r) : "f"(x));
    return __uint_as_float(r);
}

// ---------- cp.async 16B ----------
__device__ __forceinline__ void cp16(uint32_t dst_smem, const void* src) {
    asm volatile("cp.async.cg.shared.global [%0], [%1], 16;" :: "r"(dst_smem), "l"(src) : "memory");
}
__device__ __forceinline__ void cp_commit() { asm volatile("cp.async.commit_group;"); }
__device__ __forceinline__ void cp_wait0()  { asm volatile("cp.async.wait_group 0;" ::: "memory"); }
__device__ __forceinline__ void cp_wait1()  { asm volatile("cp.async.wait_group 1;" ::: "memory"); }

// ---------- constants ----------
constexpr int B = 512, T = 512;
constexpr long BT = (long)B * T;
constexpr int RC = 4;

// ---------- scratch ----------
__device__ __align__(16) float g_h0T[128 * BT];   // layer-0 out (tf32-rounded), [k][b*T+t]
__device__ __align__(16) float g_xp1[BT * 512];   // layer-1 preacts [b*T+t][n]
__device__ __align__(16) float g_BtT[128 * 512];  // Wih_l1^T (tf32-rounded) [k][n]
__device__ float g_pooled[B * 128];

// =======================================================================
// Layer-0 biLSTM (R5/R7-exact, PROTECTED). grid (128, 2), block 256, 2 CTAs/SM.
// =======================================================================
__global__ __launch_bounds__(256, 2) void lstm_l0(
    const float* __restrict__ x,
    const float* __restrict__ Wih_f, const float* __restrict__ Whh_f, const float* __restrict__ b_f,
    const float* __restrict__ Wih_b, const float* __restrict__ Whh_b, const float* __restrict__ b_b)
{
    const int dir = blockIdx.y;
    const int b0  = blockIdx.x * RC;
    const int tid = threadIdx.x;
    const int u   = tid >> 2;
    const int g   = tid & 3;
    const int row = g * 64 + u;

    const float* Wih = dir ? Wih_b : Wih_f;
    const float* Whh = dir ? Whh_b : Whh_f;
    const float* bb  = dir ? b_b   : b_f;

    __shared__ __align__(16) float h_s[2][RC * 64];
    __shared__ __align__(16) float4 x_s[2][RC];
    __shared__ __align__(16) float hist[RC][64][36];

    ULL w2[32];
    {
        const ULL* wp = (const ULL*)(Whh + row * 64);
        #pragma unroll
        for (int i = 0; i < 32; i++) w2[i] = wp[i];
    }
    const float4 wih = *(const float4*)(Wih + row * 4);
    const float bias = bb[row];

    const int lane = tid & 31;
    const int qb   = lane & ~3;

    for (int i = tid; i < RC * 64; i += 256) h_s[0][i] = 0.f;
    if (tid < RC) {
        const int t0 = dir ? (T - 1) : 0;
        x_s[0][tid] = *(const float4*)(x + ((long)(b0 + tid) * T + t0) * 4);
    }
    __syncthreads();

    float c[RC] = {0.f, 0.f, 0.f, 0.f};
    int p = 0;

    for (int s = 0; s < T; s++) {
        const int t = dir ? (T - 1 - s) : s;
        if (tid < RC) {
            const int sn = (s + 1 < T) ? s + 1 : s;
            const int tn = dir ? (T - 1 - sn) : sn;
            x_s[p ^ 1][tid] = *(const float4*)(x + ((long)(b0 + tid) * T + tn) * 4);
        }

        float pre[RC];
        #pragma unroll
        for (int j = 0; j < RC; j++) {
            ULL a0 = 0, a1 = 0;
            const ulonglong2* h4 = (const ulonglong2*)(h_s[p] + j * 64);
            #pragma unroll
            for (int k = 0; k < 16; k++) {
                ulonglong2 hv = h4[k];
                ffma2(a0, w2[2 * k],     hv.x);
                ffma2(a1, w2[2 * k + 1], hv.y);
            }
            const float2 f0 = unpack2(a0), f1 = unpack2(a1);
            const float4 xv = x_s[p][j];
            pre[j] = f0.x + f0.y + f1.x + f1.y + bias
                   + wih.x * xv.x + wih.y * xv.y + wih.z * xv.z + wih.w * xv.w;
        }

        #pragma unroll
        for (int j = 0; j < RC; j++) {
            const float act = (g == 2) ? tanh_ap(pre[j]) : sig_ap(pre[j]);
            const float iv = __shfl_sync(0xffffffffu, act, qb + 0);
            const float fv = __shfl_sync(0xffffffffu, act, qb + 1);
            const float gv = __shfl_sync(0xffffffffu, act, qb + 2);
            const float ov = __shfl_sync(0xffffffffu, act, qb + 3);
            c[j] = fmaf(fv, c[j], iv * gv);
            const float h = ov * tanh_ap(c[j]);
            if (g == 0) {
                h_s[p ^ 1][j * 64 + u] = h;
                hist[j][u][t & 31] = h;
            }
        }
        p ^= 1;
        __syncthreads();

        if ((s & 31) == 31) {
            const int tbase = t & ~31;
            #pragma unroll
            for (int w = 0; w < 8; w++) {
                const int e   = tid + w * 256;
                const int tw4 = e & 7;
                const int ju  = e >> 3;
                const int j   = ju >> 6, uu = ju & 63;
                float4 v = *(const float4*)(&hist[j][uu][tw4 * 4]);
                v.x = tf32r(v.x); v.y = tf32r(v.y); v.z = tf32r(v.z); v.w = tf32r(v.w);
                *(float4*)(g_h0T + (long)(dir * 64 + uu) * BT + (long)(b0 + j) * T + tbase + tw4 * 4) = v;
            }
            __syncthreads();
        }
    }
}

// =======================================================================
// Prep: g_BtT[k][n] = tf32(Wih_l1[n][k])   (n = dir*256 + gate_row)
// =======================================================================
__global__ void prep_btT(const float* __restrict__ Wf, const float* __restrict__ Wb)
{
    const int idx = blockIdx.x * 512 + threadIdx.x;   // 65536
    const int k = idx >> 9, n = idx & 511;
    const float* W = (n & 256) ? Wb : Wf;
    g_BtT[idx] = tf32r(W[(n & 255) * 128 + k]);
}

// =======================================================================
// xp1 GEMM via tf32 mma.sync.m16n8k8, 3-STAGE cp.async pipeline.
// CTA tile 128m x 128n, K = 4 slabs of 32, buffers mod-3; ONE barrier/slab.
// grid (2048, 4), blk 256, 2 CTAs/SM (104.4KB smem/CTA).
// =======================================================================
constexpr int FP = 136;
constexpr int KS = 32;
constexpr int SLAB = KS * FP;                 // floats per A (or B) slab
constexpr int STG_F = 2 * SLAB;               // floats per stage (A+B)
constexpr int SMEM_GEMM = 3 * STG_F * 4;      // 104448 B

__global__ __launch_bounds__(256, 2) void gemm_xp1(
    const float* __restrict__ bias_f, const float* __restrict__ bias_b)
{
    extern __shared__ float sm[];   // [stage][{A,B}][KS][FP]
    const uint32_t smB = (uint32_t)__cvta_generic_to_shared(sm);
    const int tid  = threadIdx.x;
    const int lane = tid & 31;
    const int wid  = tid >> 5;
    const int g    = lane >> 2;
    const int cc   = lane & 3;
    const int wm   = (wid & 3) * 32;
    const int wn   = (wid >> 2) * 64;
    const long m0 = (long)blockIdx.x * 128;
    const int  n0 = blockIdx.y * 128;

    float acc[2][8][4];
    #pragma unroll
    for (int i = 0; i < 2; i++)
        #pragma unroll
        for (int j = 0; j < 8; j++)
            #pragma unroll
            for (int q = 0; q < 4; q++) acc[i][j][q] = 0.f;

    const int lk  = tid >> 5;         // 0..7: k-row base (each thread loads 4 rows)
    const int lm4 = (tid & 31) * 4;   // col within row

    auto load_slab = [&](int buf, int kc) {
        const long kg = (long)kc * KS;
        const uint32_t abase = smB + (uint32_t)(buf * STG_F) * 4;
        const uint32_t bbase = abase + (uint32_t)SLAB * 4;
        #pragma unroll
        for (int i = 0; i < 4; i++) {
            const int k = lk + i * 8;
            cp16(abase + (uint32_t)(k * FP + lm4) * 4, g_h0T + (kg + k) * BT + m0 + lm4);
        }
        #pragma unroll
        for (int i = 0; i < 4; i++) {
            const int k = lk + i * 8;
            cp16(bbase + (uint32_t)(k * FP + lm4) * 4, g_BtT + (kg + k) * 512 + n0 + lm4);
        }
    };

    load_slab(0, 0); cp_commit();
    load_slab(1, 1); cp_commit();

    for (int kc = 0; kc < 4; kc++) {
        if (kc == 3) cp_wait0(); else cp_wait1();   // slab kc's group complete
        __syncthreads();                            // all warps past slab kc-1
        if (kc + 2 < 4) { load_slab((kc + 2) % 3, kc + 2); cp_commit(); }

        const float* As = sm + (kc % 3) * STG_F;
        const float* Bs = As + SLAB;
        #pragma unroll
        for (int kk = 0; kk < KS / 8; kk++) {
            const float* abase = As + (kk * 8 + cc) * FP + wm + g;
            uint32_t a0[2], a1[2], a2[2], a3[2];
            #pragma unroll
            for (int i = 0; i < 2; i++) {
                const float* ap = abase + 16 * i;
                a0[i] = __float_as_uint(ap[0]);
                a1[i] = __float_as_uint(ap[8]);
                a2[i] = __float_as_uint(ap[4 * FP]);
                a3[i] = __float_as_uint(ap[4 * FP + 8]);
            }
            const float* bbase = Bs + (kk * 8 + cc) * FP + wn + g;
            uint32_t b0[8], b1[8];
            #pragma unroll
            for (int j = 0; j < 8; j++) {
                b0[j] = __float_as_uint(bbase[8 * j]);
                b1[j] = __float_as_uint(bbase[8 * j + 4 * FP]);
            }
            #pragma unroll
            for (int i = 0; i < 2; i++)
                #pragma unroll
                for (int j = 0; j < 8; j++) {
                    asm("mma.sync.aligned.m16n8k8.row.col.f32.tf32.tf32.f32 "
                        "{%0,%1,%2,%3}, {%4,%5,%6,%7}, {%8,%9}, {%0,%1,%2,%3};"
                        : "+f"(acc[i][j][0]), "+f"(acc[i][j][1]),
                          "+f"(acc[i][j][2]), "+f"(acc[i][j][3])
                        : "r"(a0[i]), "r"(a1[i]), "r"(a2[i]), "r"(a3[i]),
                          "r"(b0[j]), "r"(b1[j]));
                }
        }
    }

    // epilogue: + bias, ULL stores
    const float* bp = (n0 & 256) ? bias_b : bias_f;
    float bn0[8], bn1[8];
    #pragma unroll
    for (int j = 0; j < 8; j++) {
        const int n = ((n0 & 255) + wn + 8 * j + cc * 2);
        bn0[j] = bp[n & 255];
        bn1[j] = bp[(n + 1) & 255];
    }
    #pragma unroll
    for (int i = 0; i < 2; i++) {
        const long mrow = m0 + wm + 16 * i + g;
        float* r0 = g_xp1 + mrow * 512;
        float* r1 = r0 + 8 * 512;
        #pragma unroll
        for (int j = 0; j < 8; j++) {
            const int n = n0 + wn + 8 * j + cc * 2;
            *(ULL*)(r0 + n) = pack2(acc[i][j][0] + bn0[j], acc[i][j][1] + bn1[j]);
            *(ULL*)(r1 + n) = pack2(acc[i][j][2] + bn0[j], acc[i][j][3] + bn1[j]);
        }
    }
}

// =======================================================================
// Layer-1 biLSTM (R8-exact, PROTECTED). grid (128, 2), block 256, 2 CTAs/SM.
// =======================================================================
__global__ __launch_bounds__(256, 2) void lstm_l1(
    const float* __restrict__ Whh_f, const float* __restrict__ Whh_b)
{
    const int dir = blockIdx.y;
    const int b0  = blockIdx.x * RC;
    const int tid = threadIdx.x;
    const int u   = tid >> 2;
    const int g   = tid & 3;
    const int row = g * 64 + u;
    const float* Whh = dir ? Whh_b : Whh_f;

    __shared__ __align__(16) float h_s[2][RC * 64];
    __shared__ __align__(16) float xp_s[2][RC][4][72];

    ULL w2[32];
    {
        const ULL* wp = (const ULL*)(Whh + row * 64);
        #pragma unroll
        for (int i = 0; i < 32; i++) w2[i] = wp[i];
    }
    const int lane = tid & 31;
    const int qb   = lane & ~3;

    const int j_st  = tid >> 6;
    const int c_st  = tid & 63;
    const int g_st  = c_st >> 4;
    const int u4_st = (c_st & 15) * 4;
    const uint32_t xpsB = (uint32_t)__cvta_generic_to_shared(&xp_s[0][0][0][0]);
    const uint32_t st_off = (uint32_t)(((j_st * 4 + g_st) * 72 + u4_st) * 4);
    const uint32_t buf_stride = (uint32_t)(RC * 4 * 72 * 4);
    const float* xp_src = g_xp1 + (long)(b0 + j_st) * T * 512 + dir * 256 + c_st * 4;

    for (int i = tid; i < RC * 64; i += 256) h_s[0][i] = 0.f;

    float c[RC]    = {0.f, 0.f, 0.f, 0.f};
    float hsum[RC] = {0.f, 0.f, 0.f, 0.f};
    {
        const int t0 = dir ? (T - 1) : 0;
        cp16(xpsB + st_off, xp_src + (long)t0 * 512);
        cp_commit();
        cp_wait0();
    }
    __syncthreads();

    int p = 0;
    for (int s = 0; s < T; s++) {
        if (s + 1 < T) {
            const int tn = dir ? (T - 2 - s) : (s + 1);
            cp16(xpsB + (p ^ 1) * buf_stride + st_off, xp_src + (long)tn * 512);
            cp_commit();
        }

        float pre[RC];
        #pragma unroll
        for (int j = 0; j < RC; j++) {
            ULL a0 = 0, a1 = 0;
            const ulonglong2* h4 = (const ulonglong2*)(h_s[p] + j * 64);
            #pragma unroll
            for (int k = 0; k < 16; k++) {
                ulonglong2 hv = h4[k];
                ffma2(a0, w2[2 * k],     hv.x);
                ffma2(a1, w2[2 * k + 1], hv.y);
            }
            const float2 f0 = unpack2(a0), f1 = unpack2(a1);
            pre[j] = f0.x + f0.y + f1.x + f1.y + xp_s[p][j][g][u];
        }

        #pragma unroll
        for (int j = 0; j < RC; j++) {
            const float act = (g == 2) ? tanh_ap(pre[j]) : sig_ap(pre[j]);
            const float iv = __shfl_sync(0xffffffffu, act, qb + 0);
            const float fv = __shfl_sync(0xffffffffu, act, qb + 1);
            const float gv = __shfl_sync(0xffffffffu, act, qb + 2);
            const float ov = __shfl_sync(0xffffffffu, act, qb + 3);
            c[j] = fmaf(fv, c[j], iv * gv);
            const float h = ov * tanh_ap(c[j]);
            hsum[j] += h;
            if (g == 0) h_s[p ^ 1][j * 64 + u] = h;
        }
        cp_wait0();
        p ^= 1;
        __syncthreads();
    }

    if (g == 0) {
        #pragma unroll
        for (int j = 0; j < RC; j++)
            g_pooled[(b0 + j) * 128 + dir * 64 + u] = hsum[j];
    }
}

// =======================================================================
__global__ void fc_kernel(const float* __restrict__ fcw, const float* __restrict__ fcb,
                          float* __restrict__ out)
{
    const int gw   = (blockIdx.x * blockDim.x + threadIdx.x) >> 5;
    const int lane = threadIdx.x & 31;
    if (gw >= B) return;
    float sum = 0.f;
    #pragma unroll
    for (int qq = 0; qq < 4; qq++)
        sum += g_pooled[gw * 128 + qq * 32 + lane] * fcw[qq * 32 + lane];
    #pragma unroll
    for (int o = 16; o; o >>= 1) sum += __shfl_xor_sync(0xffffffffu, sum, o);
    if (lane == 0) out[gw] = sum * (1.f / 512.f) + fcb[0];
}

// =======================================================================
extern "C" void kernel_launch(void* const* d_in, const int* in_sizes, int n_in,
                              void* d_out, int out_size)
{
    const float* x     = (const float*)d_in[0];
    const float* Wih0f = (const float*)d_in[1];
    const float* Whh0f = (const float*)d_in[2];
    const float* b0f   = (const float*)d_in[3];
    const float* Wih0b = (const float*)d_in[4];
    const float* Whh0b = (const float*)d_in[5];
    const float* b0b   = (const float*)d_in[6];
    const float* Wih1f = (const float*)d_in[7];
    const float* Whh1f = (const float*)d_in[8];
    const float* b1f   = (const float*)d_in[9];
    const float* Wih1b = (const float*)d_in[10];
    const float* Whh1b = (const float*)d_in[11];
    const float* b1b   = (const float*)d_in[12];
    const float* fcw   = (const float*)d_in[13];
    const float* fcb   = (const float*)d_in[14];

    prep_btT<<<128, 512>>>(Wih1f, Wih1b);
    lstm_l0<<<dim3(B / RC, 2), 256>>>(x, Wih0f, Whh0f, b0f, Wih0b, Whh0b, b0b);
    cudaFuncSetAttribute(gemm_xp1, cudaFuncAttributeMaxDynamicSharedMemorySize, SMEM_GEMM);
    gemm_xp1<<<dim3(2048, 4), 256, SMEM_GEMM>>>(b1f, b1b);
    lstm_l1<<<dim3(B / RC, 2), 256>>>(Whh1f, Whh1b);
    fc_kernel<<<32, 512>>>(fcw, fcb, (float*)d_out);
}